// round 16
// baseline (speedup 1.0000x reference)
#include <cuda_runtime.h>
#include <math.h>
#include <stdint.h>

#define B_   4096
#define M_   16
#define C_   1000
#define EMB_ 100
#define EPAD 101
#define K_   1000
#define NL_  4
#define GRID_ 592

// output layout (tuple-order concat, fp32)
#define O_POST  0
#define O_CHILD 4096000
#define O_CONF  4096001
#define O_ENS   4096002
#define O_WMS   4096003
#define O_TC    4161539

typedef unsigned long long u64;

// scratch
__device__ float g_emb[M_ * EMB_];
__device__ float g_wm [B_ * M_];
__device__ float g_pw [B_ * M_];
__device__ float g_wms[B_ * M_];
__device__ __align__(16) float g_part[B_ * 4];
__device__ unsigned int g_ctr;

__device__ __forceinline__ void cp16(uint32_t d, const void* s, int nbytes) {
    asm volatile("cp.async.cg.shared.global [%0], [%1], 16, %2;\n"
                 :: "r"(d), "l"(s), "r"(nbytes));
}
__device__ __forceinline__ u64 ffma2(u64 a, u64 b, u64 c) {
    u64 d;
    asm("fma.rn.f32x2 %0, %1, %2, %3;" : "=l"(d) : "l"(a), "l"(b), "l"(c));
    return d;
}
__device__ __forceinline__ float hadd2(u64 a) {
    float lo, hi;
    asm("mov.b64 {%0, %1}, %2;" : "=f"(lo), "=f"(hi) : "l"(a));
    return lo + hi;
}

// ---------------------------------------------------------------------------
// Kernel A: emb[m][e] = relu(model_emb[m,:] . w2[e,:] + b2[e])
// ---------------------------------------------------------------------------
__global__ void k_emb(const float* __restrict__ me, const float* __restrict__ w2,
                      const float* __restrict__ b2) {
    int m = blockIdx.x;
    int wid = threadIdx.x >> 5, lane = threadIdx.x & 31;
    int e = blockIdx.y * 8 + wid;
    if (e >= EMB_) return;
    const float* mer = me + m * K_;
    const float* w2r = w2 + e * K_;
    float acc = 0.f;
    #pragma unroll
    for (int i = 0; i < 32; i++) {
        int k = lane + (i << 5);
        if (k < K_) acc += mer[k] * w2r[k];
    }
    #pragma unroll
    for (int off = 16; off; off >>= 1)
        acc += __shfl_xor_sync(0xffffffffu, acc, off);
    if (lane == 0) g_emb[m * EMB_ + e] = fmaxf(acc + b2[e], 0.f);
}

// resets the completion counter used by k_main's fused final reduce
__global__ void k_dummy() { if (threadIdx.x == 0) g_ctr = 0u; }

// ---------------------------------------------------------------------------
// Kernel B: routing (unchanged). 128 blocks x 256 threads, 4 rows/warp,
// f32x2 FMAs, fold-exchange reduction, cp.async double buffer.
// ---------------------------------------------------------------------------
#define CE_ 4

__global__ __launch_bounds__(256, 1)
void k_route(const float* __restrict__ x_in, const float* __restrict__ w1,
             const float* __restrict__ b1, const float* __restrict__ w3,
             const float* __restrict__ b3, float* __restrict__ out) {
    __shared__ __align__(16) float w_s[2][CE_ * 1024];   // 32 KB
    __shared__ float emb_s[M_ * EPAD];
    __shared__ float b1_s[EMB_];
    __shared__ float w3_s[M_ * M_];
    __shared__ float b3_s[M_];
    __shared__ float wtmp[32 * M_];

    int tid = threadIdx.x, wid = tid >> 5, lane = tid & 31;
    int base = blockIdx.x * 32;
    int m = lane & 15, h = lane >> 4;

    for (int i = tid; i < M_ * EMB_; i += 256) {
        int mm = i / EMB_, ee = i - mm * EMB_;
        emb_s[mm * EPAD + ee] = g_emb[i];
    }
    if (tid < EMB_) b1_s[tid] = b1[tid];
    if (tid < M_ * M_) w3_s[tid] = w3[tid];
    if (tid < M_) b3_s[tid] = b3[tid];

    u64 xq[4][16];
    #pragma unroll
    for (int r = 0; r < 4; r++) {
        const float* xp = x_in + (size_t)(base + 4 * wid + r) * K_;
        #pragma unroll
        for (int i = 0; i < 8; i++) {
            int k = 4 * lane + 128 * i;
            if (k < K_) {
                ulonglong2 t = *(const ulonglong2*)(xp + k);
                xq[r][2 * i] = t.x; xq[r][2 * i + 1] = t.y;
            } else {
                xq[r][2 * i] = 0ull; xq[r][2 * i + 1] = 0ull;
            }
        }
    }

    uint32_t wb0 = (uint32_t)__cvta_generic_to_shared(&w_s[0][0]);
    uint32_t wb1 = (uint32_t)__cvta_generic_to_shared(&w_s[1][0]);

    #define STAGE(c, wb) do {                                                  \
        int ec_ = (c) * CE_;                                                   \
        _Pragma("unroll")                                                      \
        for (int j_ = 0; j_ < 4; j_++) {                                       \
            int f4_ = j_ * 256 + tid;                                          \
            int el_ = f4_ >> 8, c4_ = f4_ & 255;                               \
            const float* src_ = w1 + (size_t)(ec_ + el_) * K_                  \
                                  + ((c4_ < 250) ? c4_ * 4 : 0);               \
            int nb_ = (c4_ < 250) ? 16 : 0;                                    \
            cp16((wb) + (uint32_t)((el_ * 1024 + c4_ * 4) * 4), src_, nb_);    \
        }                                                                      \
        asm volatile("cp.async.commit_group;\n");                              \
    } while (0)

    STAGE(0, wb0);

    float score0 = 0.f, score1 = 0.f, score2 = 0.f, score3 = 0.f;

    for (int c = 0; c < 25; c++) {
        asm volatile("cp.async.wait_group 0;\n");
        __syncthreads();
        if (c + 1 < 25) STAGE(c + 1, (c & 1) ? wb0 : wb1);
        const float* wbp = w_s[c & 1];

        #pragma unroll
        for (int ep = 0; ep < 2; ep++) {
            const ulonglong2* w0p = (const ulonglong2*)(wbp + (2 * ep) * 1024);
            const ulonglong2* w1p = (const ulonglong2*)(wbp + (2 * ep + 1) * 1024);
            u64 A[8];
            #pragma unroll
            for (int j = 0; j < 8; j++) A[j] = 0ull;
            #pragma unroll
            for (int i = 0; i < 8; i++) {
                int idx = lane + 32 * i;
                ulonglong2 wa = w0p[idx];
                ulonglong2 wc = w1p[idx];
                #pragma unroll
                for (int r = 0; r < 4; r++) {
                    A[r]     = ffma2(wa.x, xq[r][2 * i],     A[r]);
                    A[r]     = ffma2(wa.y, xq[r][2 * i + 1], A[r]);
                    A[4 + r] = ffma2(wc.x, xq[r][2 * i],     A[4 + r]);
                    A[4 + r] = ffma2(wc.y, xq[r][2 * i + 1], A[4 + r]);
                }
            }
            float y0, y1, y2, y3;
            {
                float a00 = hadd2(A[0]), a01 = hadd2(A[1]);
                float a02 = hadd2(A[2]), a03 = hadd2(A[3]);
                float a10 = hadd2(A[4]), a11 = hadd2(A[5]);
                float a12 = hadd2(A[6]), a13 = hadd2(A[7]);
                y0 = (h ? a10 : a00) + __shfl_xor_sync(0xffffffffu, h ? a00 : a10, 16);
                y1 = (h ? a11 : a01) + __shfl_xor_sync(0xffffffffu, h ? a01 : a11, 16);
                y2 = (h ? a12 : a02) + __shfl_xor_sync(0xffffffffu, h ? a02 : a12, 16);
                y3 = (h ? a13 : a03) + __shfl_xor_sync(0xffffffffu, h ? a03 : a13, 16);
            }
            #pragma unroll
            for (int off = 8; off; off >>= 1) {
                y0 += __shfl_xor_sync(0xffffffffu, y0, off);
                y1 += __shfl_xor_sync(0xffffffffu, y1, off);
                y2 += __shfl_xor_sync(0xffffffffu, y2, off);
                y3 += __shfl_xor_sync(0xffffffffu, y3, off);
            }
            int elh = c * CE_ + 2 * ep + h;
            float bias = b1_s[elh];
            float em   = emb_s[m * EPAD + elh];
            score0 += fmaxf(y0 + bias, 0.f) * em;
            score1 += fmaxf(y1 + bias, 0.f) * em;
            score2 += fmaxf(y2 + bias, 0.f) * em;
            score3 += fmaxf(y3 + bias, 0.f) * em;
        }
    }

    score0 += __shfl_xor_sync(0xffffffffu, score0, 16);
    score1 += __shfl_xor_sync(0xffffffffu, score1, 16);
    score2 += __shfl_xor_sync(0xffffffffu, score2, 16);
    score3 += __shfl_xor_sync(0xffffffffu, score3, 16);

    float acc0 = b3_s[m], acc1 = acc0, acc2 = acc0, acc3 = acc0;
    #pragma unroll
    for (int m2 = 0; m2 < M_; m2++) {
        float w = w3_s[m * M_ + m2];
        int src = (lane & 16) | m2;
        acc0 += w * __shfl_sync(0xffffffffu, score0, src);
        acc1 += w * __shfl_sync(0xffffffffu, score1, src);
        acc2 += w * __shfl_sync(0xffffffffu, score2, src);
        acc3 += w * __shfl_sync(0xffffffffu, score3, src);
    }
    float wg0 = fmaxf(acc0, 0.f) + log1pf(__expf(-fabsf(acc0)));
    float wg1 = fmaxf(acc1, 0.f) + log1pf(__expf(-fabsf(acc1)));
    float wg2 = fmaxf(acc2, 0.f) + log1pf(__expf(-fabsf(acc2)));
    float wg3 = fmaxf(acc3, 0.f) + log1pf(__expf(-fabsf(acc3)));

    float rs0 = wg0, rs1 = wg1, rs2 = wg2, rs3 = wg3;
    #pragma unroll
    for (int off = 8; off; off >>= 1) {
        rs0 += __shfl_xor_sync(0xffffffffu, rs0, off);
        rs1 += __shfl_xor_sync(0xffffffffu, rs1, off);
        rs2 += __shfl_xor_sync(0xffffffffu, rs2, off);
        rs3 += __shfl_xor_sync(0xffffffffu, rs3, off);
    }
    float wm0 = wg0 / fmaxf(rs0, 1e-12f);
    float wm1 = wg1 / fmaxf(rs1, 1e-12f);
    float wm2 = wg2 / fmaxf(rs2, 1e-12f);
    float wm3 = wg3 / fmaxf(rs3, 1e-12f);

    float mx0 = wm0, mx1 = wm1, mx2 = wm2, mx3 = wm3;
    #pragma unroll
    for (int off = 8; off; off >>= 1) {
        mx0 = fmaxf(mx0, __shfl_xor_sync(0xffffffffu, mx0, off));
        mx1 = fmaxf(mx1, __shfl_xor_sync(0xffffffffu, mx1, off));
        mx2 = fmaxf(mx2, __shfl_xor_sync(0xffffffffu, mx2, off));
        mx3 = fmaxf(mx3, __shfl_xor_sync(0xffffffffu, mx3, off));
    }
    float ex0 = __expf(wm0 - mx0), ex1 = __expf(wm1 - mx1);
    float ex2 = __expf(wm2 - mx2), ex3 = __expf(wm3 - mx3);
    float es0 = ex0, es1 = ex1, es2 = ex2, es3 = ex3;
    #pragma unroll
    for (int off = 8; off; off >>= 1) {
        es0 += __shfl_xor_sync(0xffffffffu, es0, off);
        es1 += __shfl_xor_sync(0xffffffffu, es1, off);
        es2 += __shfl_xor_sync(0xffffffffu, es2, off);
        es3 += __shfl_xor_sync(0xffffffffu, es3, off);
    }
    float wmsv[4] = {ex0 / es0, ex1 / es1, ex2 / es2, ex3 / es3};
    float wmv [4] = {wm0, wm1, wm2, wm3};

    if (lane < 16) {
        int lr = 4 * wid;
        #pragma unroll
        for (int r = 0; r < 4; r++) {
            int row = base + lr + r;
            g_wm [row * M_ + m] = wmv[r];
            g_wms[row * M_ + m] = wmsv[r];
            out[O_WMS + row * M_ + m] = wmsv[r];
            wtmp[(lr + r) * M_ + m] = wmv[r];
        }
    }
    __syncthreads();

    if (tid < 32) {
        float v[M_], pw[M_];
        #pragma unroll
        for (int j = 0; j < M_; j++) { v[j] = wtmp[tid * M_ + j]; pw[j] = 0.f; }
        float ssum = 0.f;
        #pragma unroll
        for (int it = 0; it < NL_; it++) {
            int bi = 0; float bv = -1.f;
            #pragma unroll
            for (int j = 0; j < M_; j++) if (v[j] > bv) { bv = v[j]; bi = j; }
            pw[bi] = bv; ssum += bv; v[bi] = -2.f;
        }
        float inv = 1.f / fmaxf(ssum, 1e-12f);
        int row2 = base + tid;
        #pragma unroll
        for (int j = 0; j < M_; j++) g_pw[row2 * M_ + j] = pw[j] * inv;
    }
}

// ---------------------------------------------------------------------------
// Kernel C: PERSISTENT streamer (R14 structure, __ldcs restored — the R15
// __ldg experiment cost 11.5us; evict-first is required for this stream).
// One addition: the last row's chunk-3 prefetch (never consumed) is guarded
// out, saving 9.5 MB (3.6%) of wasted DRAM traffic.
// ---------------------------------------------------------------------------
__global__ __launch_bounds__(256, 4)
void k_main(const float* __restrict__ y, const int* __restrict__ labels,
            float* __restrict__ out) {
    __shared__ float wm_sh[2][M_], pw_sh[2][M_];
    __shared__ float red[17][8];
    __shared__ float fin[17];
    __shared__ int islast;

    int tid = threadIdx.x, lane = tid & 31, wid = tid >> 5;
    int b0 = blockIdx.x;
    int nrows = (B_ - b0 + GRID_ - 1) / GRID_;

    const float4* csrc = (const float4*)(y + (size_t)b0 * (M_ * C_));

    float4 va[4], vb[4];
    if (tid < 250) {
        #pragma unroll
        for (int j = 0; j < 4; j++) va[j] = __ldcs(csrc + j * 250 + tid);
    }

    int lab_c = 0;
    float wms_c = 0.f, yl_c = 0.f;
    if (tid < 16) {
        lab_c = __ldg(labels + b0);
        wm_sh[0][tid] = g_wm[b0 * M_ + tid];
        pw_sh[0][tid] = g_pw[b0 * M_ + tid];
        wms_c = g_wms[b0 * M_ + tid];
    }
    __syncthreads();
    if (tid < 16) yl_c = __ldg(y + (size_t)b0 * (M_ * C_) + tid * C_ + lab_c);

    for (int i = 0; i < nrows; i++) {
        int cs = i & 1;
        int brow = b0 + i * GRID_;
        bool hn = (i + 1) < nrows;
        int bn = hn ? (brow + GRID_) : b0;
        const float4* nsrc = (const float4*)(y + (size_t)bn * (M_ * C_));

        // next-row metadata (independent LDGs, consumed late)
        int lab_n = 0;
        float wm_n = 0.f, pw_n = 0.f, wms_n = 0.f;
        if (tid < 16) {
            lab_n = __ldg(labels + bn);
            wm_n  = g_wm [bn * M_ + tid];
            pw_n  = g_pw [bn * M_ + tid];
            wms_n = g_wms[bn * M_ + tid];
        }

        float sumS = 0.f;
        float s0 = 0, s1 = 0, s2 = 0, s3 = 0;
        float p0 = 0, p1 = 0, p2 = 0, p3 = 0;

        // chunk c: prefetch into 'pf' (if dopf), compute from 'cb', then
        // per-chunk butterfly of the 4 completed model exp-sums.
        #define MCHUNK(c, cb, pf, psrc, pc, dopf) do {                         \
            if ((dopf) && tid < 250) {                                         \
                _Pragma("unroll")                                              \
                for (int j_ = 0; j_ < 4; j_++)                                 \
                    pf[j_] = __ldcs((psrc) + ((pc) * 4 + j_) * 250 + tid);     \
            }                                                                  \
            float e0 = 0.f, e1 = 0.f, e2 = 0.f, e3 = 0.f;                      \
            if (tid < 250) {                                                   \
                _Pragma("unroll")                                              \
                for (int j_ = 0; j_ < 4; j_++) {                               \
                    int mm = (c) * 4 + j_;                                     \
                    float4 v = cb[j_];                                         \
                    float wm = wm_sh[cs][mm];                                  \
                    s0 += wm * v.x; s1 += wm * v.y;                            \
                    s2 += wm * v.z; s3 += wm * v.w;                            \
                    float pw = pw_sh[cs][mm];                                  \
                    if (pw != 0.f) {                                           \
                        p0 += pw * v.x; p1 += pw * v.y;                        \
                        p2 += pw * v.z; p3 += pw * v.w;                        \
                    }                                                          \
                    float es = __expf(v.x) + __expf(v.y)                       \
                             + __expf(v.z) + __expf(v.w);                      \
                    if (j_ == 0) e0 = es; else if (j_ == 1) e1 = es;           \
                    else if (j_ == 2) e2 = es; else e3 = es;                   \
                }                                                              \
            }                                                                  \
            _Pragma("unroll")                                                  \
            for (int off = 16; off; off >>= 1) {                               \
                e0 += __shfl_xor_sync(0xffffffffu, e0, off);                   \
                e1 += __shfl_xor_sync(0xffffffffu, e1, off);                   \
                e2 += __shfl_xor_sync(0xffffffffu, e2, off);                   \
                e3 += __shfl_xor_sync(0xffffffffu, e3, off);                   \
            }                                                                  \
            if (lane == 0) {                                                   \
                red[(c) * 4 + 0][wid] = e0;                                    \
                red[(c) * 4 + 1][wid] = e1;                                    \
                red[(c) * 4 + 2][wid] = e2;                                    \
                red[(c) * 4 + 3][wid] = e3;                                    \
            }                                                                  \
        } while (0)

        MCHUNK(0, va, vb, csrc, 1, true);
        MCHUNK(1, vb, va, csrc, 2, true);
        MCHUNK(2, va, vb, csrc, 3, true);
        MCHUNK(3, vb, va, nsrc, 0, hn);   // next row's chunk 0 only if needed

        // publish next row's wm/pw into the opposite parity slot
        if (tid < 16) {
            wm_sh[cs ^ 1][tid] = wm_n;
            pw_sh[cs ^ 1][tid] = pw_n;
        }

        if (tid < 250) {
            float4* ob = (float4*)(out + O_POST + (size_t)brow * C_);
            __stcs(ob + tid, make_float4(p0, p1, p2, p3));
            sumS = __expf(s0) + __expf(s1) + __expf(s2) + __expf(s3);
        }
        #pragma unroll
        for (int off = 16; off; off >>= 1)
            sumS += __shfl_xor_sync(0xffffffffu, sumS, off);
        if (lane == 0) red[16][wid] = sumS;

        __syncthreads();
        if (tid < 17) {
            float v = 0.f;
            #pragma unroll
            for (int w = 0; w < 8; w++) v += red[tid][w];
            fin[tid] = v;
        }
        __syncthreads();

        if (tid < 16) {
            const unsigned msk = 0xffffu;
            float yl  = yl_c;
            float lse = __logf(fin[tid]);
            float epl = lse - yl;
            float tcp = __expf(yl - lse);

            float mx = tcp;
            #pragma unroll
            for (int off = 8; off; off >>= 1)
                mx = fmaxf(mx, __shfl_xor_sync(msk, mx, off));
            float e = __expf(tcp - mx), den = e;
            #pragma unroll
            for (int off = 8; off; off >>= 1)
                den += __shfl_xor_sync(msk, den, off);
            float tc = e / den;
            out[O_TC + brow * M_ + tid] = tc;

            float mx2 = tc;
            #pragma unroll
            for (int off = 8; off; off >>= 1)
                mx2 = fmaxf(mx2, __shfl_xor_sync(msk, mx2, off));
            float e2 = __expf(tc - mx2), den2 = e2;
            #pragma unroll
            for (int off = 8; off; off >>= 1)
                den2 += __shfl_xor_sync(msk, den2, off);
            float t = e2 / den2;

            float x = wms_c;
            float conf  = x - x * t + log1pf(__expf(-x));
            float child = epl * x;
            float slabv = wm_sh[cs][tid] * yl;
            #pragma unroll
            for (int off = 8; off; off >>= 1) {
                conf  += __shfl_xor_sync(msk, conf,  off);
                child += __shfl_xor_sync(msk, child, off);
                slabv += __shfl_xor_sync(msk, slabv, off);
            }
            if (tid == 0) {
                g_part[brow * 4 + 0] = child;
                g_part[brow * 4 + 1] = conf;
                g_part[brow * 4 + 2] = __logf(fin[16]) - slabv;
            }
        }

        if (tid < 16 && hn)
            yl_c = __ldg(y + (size_t)bn * (M_ * C_) + tid * C_ + lab_n);
        wms_c = wms_n;
        csrc = nsrc;
    }

    __syncthreads();

    // fused final reduce: last CTA sums all partials
    if (tid == 0) {
        __threadfence();
        islast = (atomicAdd(&g_ctr, 1u) == (unsigned)(GRID_ - 1));
    }
    __syncthreads();
    if (islast) {
        __threadfence();
        float a = 0.f, bb = 0.f, cc = 0.f;
        const float4* gp = (const float4*)g_part;
        for (int i = tid; i < B_; i += 256) {
            float4 r = gp[i];
            a += r.x; bb += r.y; cc += r.z;
        }
        #pragma unroll
        for (int off = 16; off; off >>= 1) {
            a  += __shfl_xor_sync(0xffffffffu, a,  off);
            bb += __shfl_xor_sync(0xffffffffu, bb, off);
            cc += __shfl_xor_sync(0xffffffffu, cc, off);
        }
        if (lane == 0) { red[0][wid] = a; red[1][wid] = bb; red[2][wid] = cc; }
        __syncthreads();
        if (tid == 0) {
            float fa = 0.f, fb = 0.f, fc = 0.f;
            #pragma unroll
            for (int w = 0; w < 8; w++) { fa += red[0][w]; fb += red[1][w]; fc += red[2][w]; }
            out[O_CHILD] = fa / (float)(B_ * M_);
            out[O_CONF]  = fb / (float)(B_ * M_);
            out[O_ENS]   = fc / (float)B_;
        }
    }
}

// ---------------------------------------------------------------------------
extern "C" void kernel_launch(void* const* d_in, const int* in_sizes, int n_in,
                              void* d_out, int out_size) {
    const float* x_in  = (const float*)d_in[0];
    const float* y     = (const float*)d_in[1];
    const int*   labs  = (const int*)  d_in[2];
    const float* memb  = (const float*)d_in[3];
    const float* w1    = (const float*)d_in[4];
    const float* b1    = (const float*)d_in[5];
    const float* w2    = (const float*)d_in[6];
    const float* b2    = (const float*)d_in[7];
    const float* w3    = (const float*)d_in[8];
    const float* b3    = (const float*)d_in[9];
    float* out = (float*)d_out;

    k_emb  <<<dim3(M_, 13), 256>>>(memb, w2, b2);
    k_dummy<<<1, 32>>>();
    k_route<<<B_ / 32, 256>>>(x_in, w1, b1, w3, b3, out);
    k_main <<<GRID_, 256>>>(y, labs, out);     // profiled (pos 4)
}

// round 17
// speedup vs baseline: 1.4953x; 1.4953x over previous
#include <cuda_runtime.h>
#include <math.h>
#include <stdint.h>

#define B_   4096
#define M_   16
#define C_   1000
#define EMB_ 100
#define EPAD 101
#define K_   1000
#define NL_  4
#define GRID_ 592

// output layout (tuple-order concat, fp32)
#define O_POST  0
#define O_CHILD 4096000
#define O_CONF  4096001
#define O_ENS   4096002
#define O_WMS   4096003
#define O_TC    4161539

typedef unsigned long long u64;

// scratch
__device__ float g_emb[M_ * EMB_];
__device__ float g_wm [B_ * M_];
__device__ float g_pw [B_ * M_];
__device__ float g_wms[B_ * M_];
__device__ __align__(16) float g_part[B_ * 4];
__device__ unsigned int g_ctr;

__device__ __forceinline__ void cp16(uint32_t d, const void* s, int nbytes) {
    asm volatile("cp.async.cg.shared.global [%0], [%1], 16, %2;\n"
                 :: "r"(d), "l"(s), "r"(nbytes));
}
__device__ __forceinline__ u64 ffma2(u64 a, u64 b, u64 c) {
    u64 d;
    asm("fma.rn.f32x2 %0, %1, %2, %3;" : "=l"(d) : "l"(a), "l"(b), "l"(c));
    return d;
}
__device__ __forceinline__ float hadd2(u64 a) {
    float lo, hi;
    asm("mov.b64 {%0, %1}, %2;" : "=f"(lo), "=f"(hi) : "l"(a));
    return lo + hi;
}

// ---------------------------------------------------------------------------
// Kernel A: emb[m][e] = relu(model_emb[m,:] . w2[e,:] + b2[e])
// Also resets g_ctr (replaces the dummy kernel -> one fewer launch).
// ---------------------------------------------------------------------------
__global__ void k_emb(const float* __restrict__ me, const float* __restrict__ w2,
                      const float* __restrict__ b2) {
    if (blockIdx.x == 0 && blockIdx.y == 0 && threadIdx.x == 0) g_ctr = 0u;
    int m = blockIdx.x;
    int wid = threadIdx.x >> 5, lane = threadIdx.x & 31;
    int e = blockIdx.y * 8 + wid;
    if (e >= EMB_) return;
    const float* mer = me + m * K_;
    const float* w2r = w2 + e * K_;
    float acc = 0.f;
    #pragma unroll
    for (int i = 0; i < 32; i++) {
        int k = lane + (i << 5);
        if (k < K_) acc += mer[k] * w2r[k];
    }
    #pragma unroll
    for (int off = 16; off; off >>= 1)
        acc += __shfl_xor_sync(0xffffffffu, acc, off);
    if (lane == 0) g_emb[m * EMB_ + e] = fmaxf(acc + b2[e], 0.f);
}

// ---------------------------------------------------------------------------
// Kernel B: routing (R14 verbatim). 128 blocks x 256 threads, 4 rows/warp,
// f32x2 FMAs, fold-exchange reduction, cp.async double buffer.
// ---------------------------------------------------------------------------
#define CE_ 4

__global__ __launch_bounds__(256, 1)
void k_route(const float* __restrict__ x_in, const float* __restrict__ w1,
             const float* __restrict__ b1, const float* __restrict__ w3,
             const float* __restrict__ b3, float* __restrict__ out) {
    __shared__ __align__(16) float w_s[2][CE_ * 1024];   // 32 KB
    __shared__ float emb_s[M_ * EPAD];
    __shared__ float b1_s[EMB_];
    __shared__ float w3_s[M_ * M_];
    __shared__ float b3_s[M_];
    __shared__ float wtmp[32 * M_];

    int tid = threadIdx.x, wid = tid >> 5, lane = tid & 31;
    int base = blockIdx.x * 32;
    int m = lane & 15, h = lane >> 4;

    for (int i = tid; i < M_ * EMB_; i += 256) {
        int mm = i / EMB_, ee = i - mm * EMB_;
        emb_s[mm * EPAD + ee] = g_emb[i];
    }
    if (tid < EMB_) b1_s[tid] = b1[tid];
    if (tid < M_ * M_) w3_s[tid] = w3[tid];
    if (tid < M_) b3_s[tid] = b3[tid];

    u64 xq[4][16];
    #pragma unroll
    for (int r = 0; r < 4; r++) {
        const float* xp = x_in + (size_t)(base + 4 * wid + r) * K_;
        #pragma unroll
        for (int i = 0; i < 8; i++) {
            int k = 4 * lane + 128 * i;
            if (k < K_) {
                ulonglong2 t = *(const ulonglong2*)(xp + k);
                xq[r][2 * i] = t.x; xq[r][2 * i + 1] = t.y;
            } else {
                xq[r][2 * i] = 0ull; xq[r][2 * i + 1] = 0ull;
            }
        }
    }

    uint32_t wb0 = (uint32_t)__cvta_generic_to_shared(&w_s[0][0]);
    uint32_t wb1 = (uint32_t)__cvta_generic_to_shared(&w_s[1][0]);

    #define STAGE(c, wb) do {                                                  \
        int ec_ = (c) * CE_;                                                   \
        _Pragma("unroll")                                                      \
        for (int j_ = 0; j_ < 4; j_++) {                                       \
            int f4_ = j_ * 256 + tid;                                          \
            int el_ = f4_ >> 8, c4_ = f4_ & 255;                               \
            const float* src_ = w1 + (size_t)(ec_ + el_) * K_                  \
                                  + ((c4_ < 250) ? c4_ * 4 : 0);               \
            int nb_ = (c4_ < 250) ? 16 : 0;                                    \
            cp16((wb) + (uint32_t)((el_ * 1024 + c4_ * 4) * 4), src_, nb_);    \
        }                                                                      \
        asm volatile("cp.async.commit_group;\n");                              \
    } while (0)

    STAGE(0, wb0);

    float score0 = 0.f, score1 = 0.f, score2 = 0.f, score3 = 0.f;

    for (int c = 0; c < 25; c++) {
        asm volatile("cp.async.wait_group 0;\n");
        __syncthreads();
        if (c + 1 < 25) STAGE(c + 1, (c & 1) ? wb0 : wb1);
        const float* wbp = w_s[c & 1];

        #pragma unroll
        for (int ep = 0; ep < 2; ep++) {
            const ulonglong2* w0p = (const ulonglong2*)(wbp + (2 * ep) * 1024);
            const ulonglong2* w1p = (const ulonglong2*)(wbp + (2 * ep + 1) * 1024);
            u64 A[8];
            #pragma unroll
            for (int j = 0; j < 8; j++) A[j] = 0ull;
            #pragma unroll
            for (int i = 0; i < 8; i++) {
                int idx = lane + 32 * i;
                ulonglong2 wa = w0p[idx];
                ulonglong2 wc = w1p[idx];
                #pragma unroll
                for (int r = 0; r < 4; r++) {
                    A[r]     = ffma2(wa.x, xq[r][2 * i],     A[r]);
                    A[r]     = ffma2(wa.y, xq[r][2 * i + 1], A[r]);
                    A[4 + r] = ffma2(wc.x, xq[r][2 * i],     A[4 + r]);
                    A[4 + r] = ffma2(wc.y, xq[r][2 * i + 1], A[4 + r]);
                }
            }
            float y0, y1, y2, y3;
            {
                float a00 = hadd2(A[0]), a01 = hadd2(A[1]);
                float a02 = hadd2(A[2]), a03 = hadd2(A[3]);
                float a10 = hadd2(A[4]), a11 = hadd2(A[5]);
                float a12 = hadd2(A[6]), a13 = hadd2(A[7]);
                y0 = (h ? a10 : a00) + __shfl_xor_sync(0xffffffffu, h ? a00 : a10, 16);
                y1 = (h ? a11 : a01) + __shfl_xor_sync(0xffffffffu, h ? a01 : a11, 16);
                y2 = (h ? a12 : a02) + __shfl_xor_sync(0xffffffffu, h ? a02 : a12, 16);
                y3 = (h ? a13 : a03) + __shfl_xor_sync(0xffffffffu, h ? a03 : a13, 16);
            }
            #pragma unroll
            for (int off = 8; off; off >>= 1) {
                y0 += __shfl_xor_sync(0xffffffffu, y0, off);
                y1 += __shfl_xor_sync(0xffffffffu, y1, off);
                y2 += __shfl_xor_sync(0xffffffffu, y2, off);
                y3 += __shfl_xor_sync(0xffffffffu, y3, off);
            }
            int elh = c * CE_ + 2 * ep + h;
            float bias = b1_s[elh];
            float em   = emb_s[m * EPAD + elh];
            score0 += fmaxf(y0 + bias, 0.f) * em;
            score1 += fmaxf(y1 + bias, 0.f) * em;
            score2 += fmaxf(y2 + bias, 0.f) * em;
            score3 += fmaxf(y3 + bias, 0.f) * em;
        }
    }

    score0 += __shfl_xor_sync(0xffffffffu, score0, 16);
    score1 += __shfl_xor_sync(0xffffffffu, score1, 16);
    score2 += __shfl_xor_sync(0xffffffffu, score2, 16);
    score3 += __shfl_xor_sync(0xffffffffu, score3, 16);

    float acc0 = b3_s[m], acc1 = acc0, acc2 = acc0, acc3 = acc0;
    #pragma unroll
    for (int m2 = 0; m2 < M_; m2++) {
        float w = w3_s[m * M_ + m2];
        int src = (lane & 16) | m2;
        acc0 += w * __shfl_sync(0xffffffffu, score0, src);
        acc1 += w * __shfl_sync(0xffffffffu, score1, src);
        acc2 += w * __shfl_sync(0xffffffffu, score2, src);
        acc3 += w * __shfl_sync(0xffffffffu, score3, src);
    }
    float wg0 = fmaxf(acc0, 0.f) + log1pf(__expf(-fabsf(acc0)));
    float wg1 = fmaxf(acc1, 0.f) + log1pf(__expf(-fabsf(acc1)));
    float wg2 = fmaxf(acc2, 0.f) + log1pf(__expf(-fabsf(acc2)));
    float wg3 = fmaxf(acc3, 0.f) + log1pf(__expf(-fabsf(acc3)));

    float rs0 = wg0, rs1 = wg1, rs2 = wg2, rs3 = wg3;
    #pragma unroll
    for (int off = 8; off; off >>= 1) {
        rs0 += __shfl_xor_sync(0xffffffffu, rs0, off);
        rs1 += __shfl_xor_sync(0xffffffffu, rs1, off);
        rs2 += __shfl_xor_sync(0xffffffffu, rs2, off);
        rs3 += __shfl_xor_sync(0xffffffffu, rs3, off);
    }
    float wm0 = wg0 / fmaxf(rs0, 1e-12f);
    float wm1 = wg1 / fmaxf(rs1, 1e-12f);
    float wm2 = wg2 / fmaxf(rs2, 1e-12f);
    float wm3 = wg3 / fmaxf(rs3, 1e-12f);

    float mx0 = wm0, mx1 = wm1, mx2 = wm2, mx3 = wm3;
    #pragma unroll
    for (int off = 8; off; off >>= 1) {
        mx0 = fmaxf(mx0, __shfl_xor_sync(0xffffffffu, mx0, off));
        mx1 = fmaxf(mx1, __shfl_xor_sync(0xffffffffu, mx1, off));
        mx2 = fmaxf(mx2, __shfl_xor_sync(0xffffffffu, mx2, off));
        mx3 = fmaxf(mx3, __shfl_xor_sync(0xffffffffu, mx3, off));
    }
    float ex0 = __expf(wm0 - mx0), ex1 = __expf(wm1 - mx1);
    float ex2 = __expf(wm2 - mx2), ex3 = __expf(wm3 - mx3);
    float es0 = ex0, es1 = ex1, es2 = ex2, es3 = ex3;
    #pragma unroll
    for (int off = 8; off; off >>= 1) {
        es0 += __shfl_xor_sync(0xffffffffu, es0, off);
        es1 += __shfl_xor_sync(0xffffffffu, es1, off);
        es2 += __shfl_xor_sync(0xffffffffu, es2, off);
        es3 += __shfl_xor_sync(0xffffffffu, es3, off);
    }
    float wmsv[4] = {ex0 / es0, ex1 / es1, ex2 / es2, ex3 / es3};
    float wmv [4] = {wm0, wm1, wm2, wm3};

    if (lane < 16) {
        int lr = 4 * wid;
        #pragma unroll
        for (int r = 0; r < 4; r++) {
            int row = base + lr + r;
            g_wm [row * M_ + m] = wmv[r];
            g_wms[row * M_ + m] = wmsv[r];
            out[O_WMS + row * M_ + m] = wmsv[r];
            wtmp[(lr + r) * M_ + m] = wmv[r];
        }
    }
    __syncthreads();

    if (tid < 32) {
        float v[M_], pw[M_];
        #pragma unroll
        for (int j = 0; j < M_; j++) { v[j] = wtmp[tid * M_ + j]; pw[j] = 0.f; }
        float ssum = 0.f;
        #pragma unroll
        for (int it = 0; it < NL_; it++) {
            int bi = 0; float bv = -1.f;
            #pragma unroll
            for (int j = 0; j < M_; j++) if (v[j] > bv) { bv = v[j]; bi = j; }
            pw[bi] = bv; ssum += bv; v[bi] = -2.f;
        }
        float inv = 1.f / fmaxf(ssum, 1e-12f);
        int row2 = base + tid;
        #pragma unroll
        for (int j = 0; j < M_; j++) g_pw[row2 * M_ + j] = pw[j] * inv;
    }
}

// ---------------------------------------------------------------------------
// Kernel C: PERSISTENT streamer (R14 VERBATIM — unconditional prefetch;
// the R16 runtime-predicated prefetch demoted the register arrays to local
// memory and cost 35%. __ldcs for y (R15 showed __ldg costs 11.5us).
// ---------------------------------------------------------------------------
__global__ __launch_bounds__(256, 4)
void k_main(const float* __restrict__ y, const int* __restrict__ labels,
            float* __restrict__ out) {
    __shared__ float wm_sh[2][M_], pw_sh[2][M_];
    __shared__ float red[17][8];
    __shared__ float fin[17];
    __shared__ int islast;

    int tid = threadIdx.x, lane = tid & 31, wid = tid >> 5;
    int b0 = blockIdx.x;
    int nrows = (B_ - b0 + GRID_ - 1) / GRID_;

    const float4* csrc = (const float4*)(y + (size_t)b0 * (M_ * C_));

    float4 va[4], vb[4];
    if (tid < 250) {
        #pragma unroll
        for (int j = 0; j < 4; j++) va[j] = __ldcs(csrc + j * 250 + tid);
    }

    int lab_c = 0;
    float wms_c = 0.f, yl_c = 0.f;
    if (tid < 16) {
        lab_c = __ldg(labels + b0);
        wm_sh[0][tid] = g_wm[b0 * M_ + tid];
        pw_sh[0][tid] = g_pw[b0 * M_ + tid];
        wms_c = g_wms[b0 * M_ + tid];
    }
    __syncthreads();
    if (tid < 16) yl_c = __ldg(y + (size_t)b0 * (M_ * C_) + tid * C_ + lab_c);

    for (int i = 0; i < nrows; i++) {
        int cs = i & 1;
        int brow = b0 + i * GRID_;
        bool hn = (i + 1) < nrows;
        int bn = hn ? (brow + GRID_) : b0;
        const float4* nsrc = (const float4*)(y + (size_t)bn * (M_ * C_));

        // next-row metadata (independent LDGs, consumed late)
        int lab_n = 0;
        float wm_n = 0.f, pw_n = 0.f, wms_n = 0.f;
        if (tid < 16) {
            lab_n = __ldg(labels + bn);
            wm_n  = g_wm [bn * M_ + tid];
            pw_n  = g_pw [bn * M_ + tid];
            wms_n = g_wms[bn * M_ + tid];
        }

        float sumS = 0.f;
        float s0 = 0, s1 = 0, s2 = 0, s3 = 0;
        float p0 = 0, p1 = 0, p2 = 0, p3 = 0;

        // chunk c: prefetch into 'pf' buffer (UNCONDITIONAL), compute from
        // 'cb' buffer, then per-chunk butterfly of the 4 completed exp-sums.
        #define MCHUNK(c, cb, pf, psrc, pc) do {                               \
            if (tid < 250) {                                                   \
                _Pragma("unroll")                                              \
                for (int j_ = 0; j_ < 4; j_++)                                 \
                    pf[j_] = __ldcs((psrc) + ((pc) * 4 + j_) * 250 + tid);     \
            }                                                                  \
            float e0 = 0.f, e1 = 0.f, e2 = 0.f, e3 = 0.f;                      \
            if (tid < 250) {                                                   \
                _Pragma("unroll")                                              \
                for (int j_ = 0; j_ < 4; j_++) {                               \
                    int mm = (c) * 4 + j_;                                     \
                    float4 v = cb[j_];                                         \
                    float wm = wm_sh[cs][mm];                                  \
                    s0 += wm * v.x; s1 += wm * v.y;                            \
                    s2 += wm * v.z; s3 += wm * v.w;                            \
                    float pw = pw_sh[cs][mm];                                  \
                    if (pw != 0.f) {                                           \
                        p0 += pw * v.x; p1 += pw * v.y;                        \
                        p2 += pw * v.z; p3 += pw * v.w;                        \
                    }                                                          \
                    float es = __expf(v.x) + __expf(v.y)                       \
                             + __expf(v.z) + __expf(v.w);                      \
                    if (j_ == 0) e0 = es; else if (j_ == 1) e1 = es;           \
                    else if (j_ == 2) e2 = es; else e3 = es;                   \
                }                                                              \
            }                                                                  \
            _Pragma("unroll")                                                  \
            for (int off = 16; off; off >>= 1) {                               \
                e0 += __shfl_xor_sync(0xffffffffu, e0, off);                   \
                e1 += __shfl_xor_sync(0xffffffffu, e1, off);                   \
                e2 += __shfl_xor_sync(0xffffffffu, e2, off);                   \
                e3 += __shfl_xor_sync(0xffffffffu, e3, off);                   \
            }                                                                  \
            if (lane == 0) {                                                   \
                red[(c) * 4 + 0][wid] = e0;                                    \
                red[(c) * 4 + 1][wid] = e1;                                    \
                red[(c) * 4 + 2][wid] = e2;                                    \
                red[(c) * 4 + 3][wid] = e3;                                    \
            }                                                                  \
        } while (0)

        MCHUNK(0, va, vb, csrc, 1);
        MCHUNK(1, vb, va, csrc, 2);
        MCHUNK(2, va, vb, csrc, 3);
        MCHUNK(3, vb, va, nsrc, 0);   // next row's chunk 0 -> va

        // publish next row's wm/pw into the opposite parity slot
        if (tid < 16) {
            wm_sh[cs ^ 1][tid] = wm_n;
            pw_sh[cs ^ 1][tid] = pw_n;
        }

        if (tid < 250) {
            float4* ob = (float4*)(out + O_POST + (size_t)brow * C_);
            __stcs(ob + tid, make_float4(p0, p1, p2, p3));
            sumS = __expf(s0) + __expf(s1) + __expf(s2) + __expf(s3);
        }
        #pragma unroll
        for (int off = 16; off; off >>= 1)
            sumS += __shfl_xor_sync(0xffffffffu, sumS, off);
        if (lane == 0) red[16][wid] = sumS;

        __syncthreads();
        if (tid < 17) {
            float v = 0.f;
            #pragma unroll
            for (int w = 0; w < 8; w++) v += red[tid][w];
            fin[tid] = v;
        }
        __syncthreads();

        if (tid < 16) {
            const unsigned msk = 0xffffu;
            float yl  = yl_c;
            float lse = __logf(fin[tid]);
            float epl = lse - yl;
            float tcp = __expf(yl - lse);

            float mx = tcp;
            #pragma unroll
            for (int off = 8; off; off >>= 1)
                mx = fmaxf(mx, __shfl_xor_sync(msk, mx, off));
            float e = __expf(tcp - mx), den = e;
            #pragma unroll
            for (int off = 8; off; off >>= 1)
                den += __shfl_xor_sync(msk, den, off);
            float tc = e / den;
            out[O_TC + brow * M_ + tid] = tc;

            float mx2 = tc;
            #pragma unroll
            for (int off = 8; off; off >>= 1)
                mx2 = fmaxf(mx2, __shfl_xor_sync(msk, mx2, off));
            float e2 = __expf(tc - mx2), den2 = e2;
            #pragma unroll
            for (int off = 8; off; off >>= 1)
                den2 += __shfl_xor_sync(msk, den2, off);
            float t = e2 / den2;

            float x = wms_c;
            float conf  = x - x * t + log1pf(__expf(-x));
            float child = epl * x;
            float slabv = wm_sh[cs][tid] * yl;
            #pragma unroll
            for (int off = 8; off; off >>= 1) {
                conf  += __shfl_xor_sync(msk, conf,  off);
                child += __shfl_xor_sync(msk, child, off);
                slabv += __shfl_xor_sync(msk, slabv, off);
            }
            if (tid == 0) {
                g_part[brow * 4 + 0] = child;
                g_part[brow * 4 + 1] = conf;
                g_part[brow * 4 + 2] = __logf(fin[16]) - slabv;
            }
        }

        if (tid < 16 && hn)
            yl_c = __ldg(y + (size_t)bn * (M_ * C_) + tid * C_ + lab_n);
        wms_c = wms_n;
        csrc = nsrc;
    }

    __syncthreads();

    // fused final reduce: last CTA sums all partials
    if (tid == 0) {
        __threadfence();
        islast = (atomicAdd(&g_ctr, 1u) == (unsigned)(GRID_ - 1));
    }
    __syncthreads();
    if (islast) {
        __threadfence();
        float a = 0.f, bb = 0.f, cc = 0.f;
        const float4* gp = (const float4*)g_part;
        for (int i = tid; i < B_; i += 256) {
            float4 r = gp[i];
            a += r.x; bb += r.y; cc += r.z;
        }
        #pragma unroll
        for (int off = 16; off; off >>= 1) {
            a  += __shfl_xor_sync(0xffffffffu, a,  off);
            bb += __shfl_xor_sync(0xffffffffu, bb, off);
            cc += __shfl_xor_sync(0xffffffffu, cc, off);
        }
        if (lane == 0) { red[0][wid] = a; red[1][wid] = bb; red[2][wid] = cc; }
        __syncthreads();
        if (tid == 0) {
            float fa = 0.f, fb = 0.f, fc = 0.f;
            #pragma unroll
            for (int w = 0; w < 8; w++) { fa += red[0][w]; fb += red[1][w]; fc += red[2][w]; }
            out[O_CHILD] = fa / (float)(B_ * M_);
            out[O_CONF]  = fb / (float)(B_ * M_);
            out[O_ENS]   = fc / (float)B_;
        }
    }
}

// ---------------------------------------------------------------------------
extern "C" void kernel_launch(void* const* d_in, const int* in_sizes, int n_in,
                              void* d_out, int out_size) {
    const float* x_in  = (const float*)d_in[0];
    const float* y     = (const float*)d_in[1];
    const int*   labs  = (const int*)  d_in[2];
    const float* memb  = (const float*)d_in[3];
    const float* w1    = (const float*)d_in[4];
    const float* b1    = (const float*)d_in[5];
    const float* w2    = (const float*)d_in[6];
    const float* b2    = (const float*)d_in[7];
    const float* w3    = (const float*)d_in[8];
    const float* b3    = (const float*)d_in[9];
    float* out = (float*)d_out;

    k_emb  <<<dim3(M_, 13), 256>>>(memb, w2, b2);
    k_route<<<B_ / 32, 256>>>(x_in, w1, b1, w3, b3, out);
    k_main <<<GRID_, 256>>>(y, labs, out);
}